// round 4
// baseline (speedup 1.0000x reference)
#include <cuda_runtime.h>

// LSTM: B=512, T=512, D=32, H=64.
// One CTA (256 threads) per FOUR batch elements -> 128 CTAs, one wave, 1 CTA/SM.
// Thread g owns gate row g (weights register-resident: 16+32 f32x2 = 96 regs)
// and computes that row's pre-activation for all 4 local batches per step
// (16 independent FFMA2 chains -> latency hiding without occupancy).
// State update: thread t updates element (t&63) of local batch (t>>6).
// Sigmoid head over hs runs as a separate parallel epilogue kernel.

#define B_ 512
#define T_ 512
#define D_ 32
#define H_ 64
#define NB 4

typedef unsigned long long u64;

__device__ __forceinline__ u64 fma2(u64 a, u64 b, u64 c) {
    u64 d;
    asm("fma.rn.f32x2 %0, %1, %2, %3;" : "=l"(d) : "l"(a), "l"(b), "l"(c));
    return d;
}
__device__ __forceinline__ u64 add2(u64 a, u64 b) {
    u64 d;
    asm("add.rn.f32x2 %0, %1, %2;" : "=l"(d) : "l"(a), "l"(b));
    return d;
}
__device__ __forceinline__ float lo32(u64 a) { return __uint_as_float((unsigned)a); }
__device__ __forceinline__ float hi32(u64 a) { return __uint_as_float((unsigned)(a >> 32)); }

__device__ __forceinline__ float sigmoid_(float x) {
    return __fdividef(1.f, 1.f + __expf(-x));  // x<<0 -> 1/inf = 0, correct
}
__device__ __forceinline__ float tanh_(float x) {
    float ax = fabsf(x);
    float t = 1.f - __fdividef(2.f, __expf(2.f * ax) + 1.f);  // exact 1 at sat
    return copysignf(t, x);
}

__global__ __launch_bounds__(256, 1) void lstm_fused_kernel(
    const float* __restrict__ x,     // [B,T,D]
    const float* __restrict__ h0,    // [1,B,H]
    const float* __restrict__ c0,    // [1,B,H]
    const float* __restrict__ Wih,   // [4H,D]
    const float* __restrict__ Whh,   // [4H,H]
    const float* __restrict__ bih,   // [4H]
    const float* __restrict__ bhh,   // [4H]
    float* __restrict__ hs)          // [B,T,H]
{
    __shared__ __align__(16) float h_sm[NB][H_];
    __shared__ __align__(16) float x_sm[2][NB][D_];
    __shared__ __align__(16) float act_sm[NB][256];

    const int tid = threadIdx.x;
    const int gb0 = blockIdx.x * NB;          // first global batch of this CTA
    const int b_loc = tid >> 6;               // local batch this thread updates
    const int e = tid & 63;                   // element within h/c

    // ---- weights -> registers as packed f32x2 (row tid) ----
    u64 wih[16], whh[32];
    {
        const ulonglong2* p = reinterpret_cast<const ulonglong2*>(Wih + tid * D_);
#pragma unroll
        for (int q = 0; q < 8; q++) {
            ulonglong2 v = p[q];
            wih[2 * q] = v.x;
            wih[2 * q + 1] = v.y;
        }
        const ulonglong2* p2 = reinterpret_cast<const ulonglong2*>(Whh + tid * H_);
#pragma unroll
        for (int q = 0; q < 16; q++) {
            ulonglong2 v = p2[q];
            whh[2 * q] = v.x;
            whh[2 * q + 1] = v.y;
        }
    }
    // unified activation: gate block 2 (candidate) uses tanh = 2*sigmoid(2x)-1
    const bool is_tanh = ((tid >> 6) == 2);
    const float K = is_tanh ? 2.f : 1.f;
    const float A = is_tanh ? 2.f : 1.f;
    const float C = is_tanh ? -1.f : 0.f;
    const float bias = bih[tid] + bhh[tid];

    // state for (gb0 + b_loc, element e) -- every thread holds one c value
    float c = c0[(gb0 + b_loc) * H_ + e];
    h_sm[b_loc][e] = h0[(gb0 + b_loc) * H_ + e];
    float* hs_ptr = hs + ((long long)(gb0 + b_loc) * T_) * H_ + e;

    // x staging: warps 4..7 each own one local batch (32 floats)
    const int xw = (tid >> 5) - 4;            // 0..3 for staging warps
    const int xl = tid & 31;
    const float* x_ptr = (xw >= 0) ? (x + ((long long)(gb0 + xw) * T_) * D_) : x;
    if (xw >= 0) x_sm[0][xw][xl] = x_ptr[xl];
    __syncthreads();

    for (int t = 0; t < T_; t++) {
        // prefetch x_{t+1}
        float xn = 0.f;
        if (xw >= 0) xn = x_ptr[(t + 1 < T_ ? t + 1 : t) * D_ + xl];

        // 4 fused dots: pre[j] = Wih[row]@x_t[j] + Whh[row]@h[j] + bias
        float pre[NB];
#pragma unroll
        for (int j = 0; j < NB; j++) {
            u64 a0 = 0, a1 = 0, a2 = 0, a3 = 0;
            const ulonglong2* xv = reinterpret_cast<const ulonglong2*>(x_sm[t & 1][j]);
#pragma unroll
            for (int q = 0; q < 8; q++) {
                ulonglong2 v = xv[q];  // LDS.128 broadcast
                a0 = fma2(wih[2 * q], v.x, a0);
                a1 = fma2(wih[2 * q + 1], v.y, a1);
            }
            const ulonglong2* hv = reinterpret_cast<const ulonglong2*>(h_sm[j]);
#pragma unroll
            for (int q = 0; q < 16; q++) {
                ulonglong2 v = hv[q];  // LDS.128 broadcast
                a2 = fma2(whh[2 * q], v.x, a2);
                a3 = fma2(whh[2 * q + 1], v.y, a3);
            }
            u64 s = add2(add2(a0, a1), add2(a2, a3));
            pre[j] = lo32(s) + hi32(s) + bias;
        }
#pragma unroll
        for (int j = 0; j < NB; j++)
            act_sm[j][tid] = fmaf(A, sigmoid_(K * pre[j]), C);
        __syncthreads();  // bar1: gates visible; x_sm[t&1] now dead

        if (xw >= 0) x_sm[(t + 1) & 1][xw][xl] = xn;

        // state update: every thread owns (b_loc, e)
        {
            float iv = act_sm[b_loc][e];
            float fv = act_sm[b_loc][H_ + e];
            float gv = act_sm[b_loc][2 * H_ + e];
            float ov = act_sm[b_loc][3 * H_ + e];
            c = fv * c + iv * gv;
            float h = ov * tanh_(c);
            h_sm[b_loc][e] = h;
            hs_ptr[0] = h;
            hs_ptr += H_;
        }
        __syncthreads();  // bar2: h_sm + next-x visible
    }
}

// Epilogue: out0[b,t] = sigmoid( dot(hs[b,t,:], Wout) + bout ).
__global__ __launch_bounds__(256) void head_kernel(
    const float* __restrict__ hs,    // [B*T, H]
    const float* __restrict__ Wout,  // [H]
    const float* __restrict__ bout,  // [1]
    float* __restrict__ out0)        // [B*T]
{
    __shared__ __align__(16) float w_sm[H_];
    if (threadIdx.x < H_) w_sm[threadIdx.x] = Wout[threadIdx.x];
    __syncthreads();

    long long row = (long long)blockIdx.x * blockDim.x + threadIdx.x;
    if (row >= (long long)B_ * T_) return;

    const float4* hv = reinterpret_cast<const float4*>(hs + row * H_);
    const float4* wv = reinterpret_cast<const float4*>(w_sm);
    float acc = 0.f;
#pragma unroll
    for (int q = 0; q < H_ / 4; q++) {
        float4 h4 = hv[q];
        float4 w4 = wv[q];
        acc += h4.x * w4.x + h4.y * w4.y + h4.z * w4.z + h4.w * w4.w;
    }
    out0[row] = sigmoid_(acc + bout[0]);
}

extern "C" void kernel_launch(void* const* d_in, const int* in_sizes, int n_in,
                              void* d_out, int out_size) {
    const float* x    = (const float*)d_in[0];
    const float* h0   = (const float*)d_in[1];
    const float* c0   = (const float*)d_in[2];
    const float* Wih  = (const float*)d_in[3];
    const float* Whh  = (const float*)d_in[4];
    const float* bih  = (const float*)d_in[5];
    const float* bhh  = (const float*)d_in[6];
    const float* Wout = (const float*)d_in[7];
    const float* bout = (const float*)d_in[8];

    float* d = (float*)d_out;
    const long long BT = (long long)B_ * T_;

    float* out0 = d;
    float* hs = d;
    int write_out0 = 1;
    if ((long long)out_size >= BT * (H_ + 1)) {
        out0 = d;           // concat(output [B,T,1], hs [B,T,H]) — verified case
        hs = d + BT;
    } else if ((long long)out_size == BT * H_) {
        hs = d;
        write_out0 = 0;
    }

    lstm_fused_kernel<<<B_ / NB, 256>>>(x, h0, c0, Wih, Whh, bih, bhh, hs);
    if (write_out0) {
        int grid = (int)((BT + 255) / 256);
        head_kernel<<<grid, 256>>>(hs, Wout, bout, out0);
    }
}

// round 5
// speedup vs baseline: 1.2168x; 1.2168x over previous
#include <cuda_runtime.h>

// LSTM: B=512, T=512, D=32, H=64.
//
// Pass 1 (xproj): xg[b,t,row] = W_ih[row]@x[b,t] + b_ih[row] + b_hh[row],
//   stored PERMUTED so recurrent thread tid reads xg[bt*256 + tid] coalesced.
// Pass 2 (lstm): 256 CTAs (2 batches each), 256 threads, 2 CTAs/SM -> 1 wave.
//   Thread (q=tid&3, e=tid>>2) owns gate row q*64+e with W_hh register-resident.
//   Per step: 2 h-dots (8 interleaved FFMA2 chains), unified activation,
//   quad shfl_xor gather (lane q==0 gets i,f,g,o directly), state update,
//   ping-pong h_sm, ONE __syncthreads.
// Pass 3 (head): out0 = sigmoid(hs @ Wout + bout), parallel.

#define B_ 512
#define T_ 512
#define D_ 32
#define H_ 64
#define G4 (4 * H_)   // 256 gate rows
#define NB 2

typedef unsigned long long u64;

__device__ float g_xg[(long long)B_ * T_ * G4];   // 268 MB scratch

__device__ __forceinline__ u64 fma2(u64 a, u64 b, u64 c) {
    u64 d;
    asm("fma.rn.f32x2 %0, %1, %2, %3;" : "=l"(d) : "l"(a), "l"(b), "l"(c));
    return d;
}
__device__ __forceinline__ u64 add2(u64 a, u64 b) {
    u64 d;
    asm("add.rn.f32x2 %0, %1, %2;" : "=l"(d) : "l"(a), "l"(b));
    return d;
}
__device__ __forceinline__ float lo32(u64 a) { return __uint_as_float((unsigned)a); }
__device__ __forceinline__ float hi32(u64 a) { return __uint_as_float((unsigned)(a >> 32)); }

__device__ __forceinline__ float sigmoid_(float x) {
    return __fdividef(1.f, 1.f + __expf(-x));  // x<<0 -> 1/inf = 0, correct
}
__device__ __forceinline__ float tanh_(float x) {
    float ax = fabsf(x);
    float t = 1.f - __fdividef(2.f, __expf(2.f * ax) + 1.f);  // exact 1 at sat
    return copysignf(t, x);
}

// ---------------- Pass 1: input projection (parallel GEMM) ----------------
#define XCH 8
__global__ __launch_bounds__(256) void xproj_kernel(
    const float* __restrict__ x,    // [B*T, D]
    const float* __restrict__ Wih,  // [4H, D]
    const float* __restrict__ bih,  // [4H]
    const float* __restrict__ bhh)  // [4H]
{
    __shared__ __align__(16) float x_sm[XCH][D_];
    const int tid = threadIdx.x;
    const int row = (tid & 3) * H_ + (tid >> 2);  // permuted gate row

    u64 wih[16];
    {
        const ulonglong2* p = reinterpret_cast<const ulonglong2*>(Wih + row * D_);
#pragma unroll
        for (int qq = 0; qq < 8; qq++) {
            ulonglong2 v = p[qq];
            wih[2 * qq] = v.x;
            wih[2 * qq + 1] = v.y;
        }
    }
    const float bias = bih[row] + bhh[row];

    const long long bt0 = (long long)blockIdx.x * (B_ * T_ / 512);
    const long long bt1 = bt0 + (B_ * T_ / 512);
    for (long long bt = bt0; bt < bt1; bt += XCH) {
        // stage XCH timesteps of x (256 floats, coalesced)
        x_sm[tid >> 5][tid & 31] = x[bt * D_ + tid];
        __syncthreads();
#pragma unroll
        for (int j = 0; j < XCH; j++) {
            const ulonglong2* xv = reinterpret_cast<const ulonglong2*>(x_sm[j]);
            u64 a0 = 0, a1 = 0;
#pragma unroll
            for (int qq = 0; qq < 8; qq++) {
                ulonglong2 v = xv[qq];
                a0 = fma2(wih[2 * qq], v.x, a0);
                a1 = fma2(wih[2 * qq + 1], v.y, a1);
            }
            u64 s = add2(a0, a1);
            g_xg[(bt + j) * G4 + tid] = lo32(s) + hi32(s) + bias;
        }
        __syncthreads();
    }
}

// ---------------- Pass 2: recurrence ----------------
__global__ __launch_bounds__(256, 2) void lstm_kernel(
    const float* __restrict__ h0,   // [1,B,H]
    const float* __restrict__ c0,   // [1,B,H]
    const float* __restrict__ Whh,  // [4H,H]
    float* __restrict__ hs)         // [B,T,H]
{
    __shared__ __align__(16) float h_sm[2][NB][H_];

    const int tid = threadIdx.x;
    const int q = tid & 3;
    const int e = tid >> 2;
    const int row = q * H_ + e;
    const int b0 = blockIdx.x * NB;

    // W_hh row -> 32 packed f32x2 regs
    u64 whh[32];
    {
        const ulonglong2* p = reinterpret_cast<const ulonglong2*>(Whh + row * H_);
#pragma unroll
        for (int qq = 0; qq < 16; qq++) {
            ulonglong2 v = p[qq];
            whh[2 * qq] = v.x;
            whh[2 * qq + 1] = v.y;
        }
    }
    // unified activation: q==2 (candidate) uses tanh = 2*sigmoid(2x)-1
    const float K = (q == 2) ? 2.f : 1.f;
    const float A = (q == 2) ? 2.f : 1.f;
    const float C = (q == 2) ? -1.f : 0.f;

    float c_0 = c0[(b0 + 0) * H_ + e];      // valid state kept in q==0 lanes
    float c_1 = c0[(b0 + 1) * H_ + e];
    if (q == 0) {
        h_sm[0][0][e] = h0[(b0 + 0) * H_ + e];
        h_sm[0][1][e] = h0[(b0 + 1) * H_ + e];
    }
    float* hsp0 = hs + ((long long)(b0 + 0) * T_) * H_ + e;
    float* hsp1 = hs + ((long long)(b0 + 1) * T_) * H_ + e;

    const float* xq0 = g_xg + ((long long)(b0 + 0) * T_) * G4 + tid;
    const float* xq1 = g_xg + ((long long)(b0 + 1) * T_) * G4 + tid;
    // 2-deep xg prefetch
    float xa0 = xq0[0],  xa1 = xq1[0];
    float xb0 = xq0[G4], xb1 = xq1[G4];
    __syncthreads();

    for (int t = 0; t < T_; t++) {
        float xc0 = 0.f, xc1 = 0.f;
        if (t + 2 < T_) {
            xc0 = xq0[(t + 2) * G4];
            xc1 = xq1[(t + 2) * G4];
        }

        // two h-dots, 8 interleaved FFMA2 chains
        const ulonglong2* hv0 = reinterpret_cast<const ulonglong2*>(h_sm[t & 1][0]);
        const ulonglong2* hv1 = reinterpret_cast<const ulonglong2*>(h_sm[t & 1][1]);
        u64 a00 = 0, a01 = 0, a10 = 0, a11 = 0;
#pragma unroll
        for (int qq = 0; qq < 16; qq++) {
            ulonglong2 v0 = hv0[qq];  // LDS.128 broadcast
            ulonglong2 v1 = hv1[qq];
            a00 = fma2(whh[2 * qq], v0.x, a00);
            a01 = fma2(whh[2 * qq + 1], v0.y, a01);
            a10 = fma2(whh[2 * qq], v1.x, a10);
            a11 = fma2(whh[2 * qq + 1], v1.y, a11);
        }
        u64 s0 = add2(a00, a01);
        u64 s1 = add2(a10, a11);
        float pre0 = lo32(s0) + hi32(s0) + xa0;
        float pre1 = lo32(s1) + hi32(s1) + xa1;

        float act0 = fmaf(A, sigmoid_(K * pre0), C);
        float act1 = fmaf(A, sigmoid_(K * pre1), C);

        // quad gather: for lane q==0, (act, f, g, o) land directly
        float f0 = __shfl_xor_sync(0xffffffffu, act0, 1);
        float f1 = __shfl_xor_sync(0xffffffffu, act1, 1);
        float g0 = __shfl_xor_sync(0xffffffffu, act0, 2);
        float g1 = __shfl_xor_sync(0xffffffffu, act1, 2);
        float o0 = __shfl_xor_sync(0xffffffffu, f0, 2);
        float o1 = __shfl_xor_sync(0xffffffffu, f1, 2);

        if (q == 0) {
            c_0 = f0 * c_0 + act0 * g0;
            c_1 = f1 * c_1 + act1 * g1;
            float hh0 = o0 * tanh_(c_0);
            float hh1 = o1 * tanh_(c_1);
            h_sm[(t + 1) & 1][0][e] = hh0;
            h_sm[(t + 1) & 1][1][e] = hh1;
            hsp0[0] = hh0;
            hsp1[0] = hh1;
        }
        hsp0 += H_;
        hsp1 += H_;
        xa0 = xb0; xa1 = xb1;
        xb0 = xc0; xb1 = xc1;
        __syncthreads();  // single barrier: next-buf h_sm visible
    }
}

// ---------------- Pass 3: sigmoid head ----------------
__global__ __launch_bounds__(256) void head_kernel(
    const float* __restrict__ hs,    // [B*T, H]
    const float* __restrict__ Wout,  // [H]
    const float* __restrict__ bout,  // [1]
    float* __restrict__ out0)        // [B*T]
{
    __shared__ __align__(16) float w_sm[H_];
    if (threadIdx.x < H_) w_sm[threadIdx.x] = Wout[threadIdx.x];
    __syncthreads();

    long long rowi = (long long)blockIdx.x * blockDim.x + threadIdx.x;
    if (rowi >= (long long)B_ * T_) return;

    const float4* hv = reinterpret_cast<const float4*>(hs + rowi * H_);
    const float4* wv = reinterpret_cast<const float4*>(w_sm);
    float acc = 0.f;
#pragma unroll
    for (int qq = 0; qq < H_ / 4; qq++) {
        float4 h4 = hv[qq];
        float4 w4 = wv[qq];
        acc += h4.x * w4.x + h4.y * w4.y + h4.z * w4.z + h4.w * w4.w;
    }
    out0[rowi] = sigmoid_(acc + bout[0]);
}

extern "C" void kernel_launch(void* const* d_in, const int* in_sizes, int n_in,
                              void* d_out, int out_size) {
    const float* x    = (const float*)d_in[0];
    const float* h0   = (const float*)d_in[1];
    const float* c0   = (const float*)d_in[2];
    const float* Wih  = (const float*)d_in[3];
    const float* Whh  = (const float*)d_in[4];
    const float* bih  = (const float*)d_in[5];
    const float* bhh  = (const float*)d_in[6];
    const float* Wout = (const float*)d_in[7];
    const float* bout = (const float*)d_in[8];

    float* d = (float*)d_out;
    const long long BT = (long long)B_ * T_;

    float* out0 = d;
    float* hs = d;
    int write_out0 = 1;
    if ((long long)out_size >= BT * (H_ + 1)) {
        out0 = d;           // concat(output [B,T,1], hs [B,T,H]) — verified case
        hs = d + BT;
    } else if ((long long)out_size == BT * H_) {
        hs = d;
        write_out0 = 0;
    }

    xproj_kernel<<<512, 256>>>(x, Wih, bih, bhh);
    lstm_kernel<<<B_ / NB, 256>>>(h0, c0, Whh, hs);
    if (write_out0) {
        int grid = (int)((BT + 255) / 256);
        head_kernel<<<grid, 256>>>(hs, Wout, bout, out0);
    }
}